// round 12
// baseline (speedup 1.0000x reference)
#include <cuda_runtime.h>
#include <math.h>

// Mutual cross attention, B=8, L=2048, D=512, fp32.
// out = attn(x1, x2, x2) + attn(x2, x1, x1)   (flash-style, two passes)

#define B_   8
#define L_   2048
#define D_   512
#define BQ   32            // query rows per block
#define BK   32            // key rows per tile
#define PADF 4             // row padding in floats (row = 2064 B, shifts banks by 16B/row)
#define ROWF (D_ + PADF)   // 516 floats per smem row
#define NTH  256
#define NKT  (L_ / BK)     // 64 key tiles

// ---------- packed f32x2 FMA (Blackwell FFMA2) ----------
__device__ __forceinline__ float2 ffma2(float2 a, float2 b, float2 c) {
    float2 d;
    asm("{\n\t"
        ".reg .b64 ra, rb, rc, rd;\n\t"
        "mov.b64 ra, {%2, %3};\n\t"
        "mov.b64 rb, {%4, %5};\n\t"
        "mov.b64 rc, {%6, %7};\n\t"
        "fma.rn.f32x2 rd, ra, rb, rc;\n\t"
        "mov.b64 {%0, %1}, rd;\n\t"
        "}"
        : "=f"(d.x), "=f"(d.y)
        : "f"(a.x), "f"(a.y), "f"(b.x), "f"(b.y), "f"(c.x), "f"(c.y));
    return d;
}

// ---------- cp.async helpers ----------
__device__ __forceinline__ void cp_async16(float* smem_dst, const float* gmem_src) {
    unsigned saddr = (unsigned)__cvta_generic_to_shared(smem_dst);
    asm volatile("cp.async.cg.shared.global [%0], [%1], 16;" :: "r"(saddr), "l"(gmem_src));
}
__device__ __forceinline__ void cp_commit() { asm volatile("cp.async.commit_group;"); }
__device__ __forceinline__ void cp_wait0()  { asm volatile("cp.async.wait_group 0;"); }

template <bool ACCUM>
__global__ void __launch_bounds__(NTH, 1)
mca_attn_kernel(const float* __restrict__ Qg,   // [B, L, D] queries
                const float* __restrict__ KVg,  // [B, L, D] keys == values
                float* __restrict__ Og)         // [B, L, D]
{
    extern __shared__ float smem[];
    float* Qs  = smem;                 // BQ * ROWF
    float* KV0 = Qs  + BQ * ROWF;      // BK * ROWF
    float* KV1 = KV0 + BK * ROWF;      // BK * ROWF
    float* Ps  = KV1 + BK * ROWF;      // BQ * 33 (probabilities tile)

    const int tid = threadIdx.x;
    const int qt  = blockIdx.x;        // query tile 0..63
    const int b   = blockIdx.y;        // batch
    const int q   = tid >> 3;          // local query row 0..31
    const int s   = tid & 7;           // 8-way split: k-groups for S, d-slices for PV

    const float scale = 0.04419417382415922f;  // 1/sqrt(512)

    const float* qbase = Qg  + ((size_t)b * L_ + (size_t)qt * BQ) * D_;
    const float* kbase = KVg + (size_t)b * L_ * D_;

    // --- async load Q tile + KV tile 0 (32 rows x 128 float4 each; 16 per thread) ---
    #pragma unroll
    for (int i = 0; i < 16; ++i) {
        int f  = tid + i * NTH;        // float4 index 0..4095
        int r  = f >> 7;
        int c4 = f & 127;
        cp_async16(Qs + r * ROWF + c4 * 4, qbase + r * D_ + c4 * 4);
    }
    #pragma unroll
    for (int i = 0; i < 16; ++i) {
        int f  = tid + i * NTH;
        int r  = f >> 7;
        int c4 = f & 127;
        cp_async16(KV0 + r * ROWF + c4 * 4, kbase + r * D_ + c4 * 4);
    }
    cp_commit();

    // accumulator: this thread owns query row q, interleaved d-slices d4 = s + 8g
    float2 acc[32];
    #pragma unroll
    for (int j = 0; j < 32; ++j) acc[j] = make_float2(0.f, 0.f);
    float m = -INFINITY;
    float l = 0.f;

    cp_wait0();
    __syncthreads();

    for (int kt = 0; kt < NKT; ++kt) {
        float* cur = (kt & 1) ? KV1 : KV0;
        float* nxt = (kt & 1) ? KV0 : KV1;

        // prefetch next KV tile into the buffer we finished with last iteration
        if (kt + 1 < NKT) {
            const float* g = kbase + (size_t)(kt + 1) * BK * D_;
            #pragma unroll
            for (int i = 0; i < 16; ++i) {
                int f  = tid + i * NTH;
                int r  = f >> 7;
                int c4 = f & 127;
                cp_async16(nxt + r * ROWF + c4 * 4, g + r * D_ + c4 * 4);
            }
            cp_commit();
        }

        // ---- S = Q . K^T on this tile: thread computes S[q][s + 8c], c = 0..3 ----
        float2 sa0 = make_float2(0.f, 0.f), sa1 = sa0, sa2 = sa0, sa3 = sa0;
        const float4* qrow = reinterpret_cast<const float4*>(Qs + q * ROWF);
        const float4* k0   = reinterpret_cast<const float4*>(cur + (s +  0) * ROWF);
        const float4* k1   = reinterpret_cast<const float4*>(cur + (s +  8) * ROWF);
        const float4* k2   = reinterpret_cast<const float4*>(cur + (s + 16) * ROWF);
        const float4* k3   = reinterpret_cast<const float4*>(cur + (s + 24) * ROWF);
        #pragma unroll 4
        for (int dq = 0; dq < D_ / 4; ++dq) {
            float4 qv = qrow[dq];
            float2 ql = make_float2(qv.x, qv.y);
            float2 qh = make_float2(qv.z, qv.w);
            float4 kv;
            kv = k0[dq];
            sa0 = ffma2(ql, make_float2(kv.x, kv.y), sa0);
            sa0 = ffma2(qh, make_float2(kv.z, kv.w), sa0);
            kv = k1[dq];
            sa1 = ffma2(ql, make_float2(kv.x, kv.y), sa1);
            sa1 = ffma2(qh, make_float2(kv.z, kv.w), sa1);
            kv = k2[dq];
            sa2 = ffma2(ql, make_float2(kv.x, kv.y), sa2);
            sa2 = ffma2(qh, make_float2(kv.z, kv.w), sa2);
            kv = k3[dq];
            sa3 = ffma2(ql, make_float2(kv.x, kv.y), sa3);
            sa3 = ffma2(qh, make_float2(kv.z, kv.w), sa3);
        }
        float sv0 = (sa0.x + sa0.y) * scale;
        float sv1 = (sa1.x + sa1.y) * scale;
        float sv2 = (sa2.x + sa2.y) * scale;
        float sv3 = (sa3.x + sa3.y) * scale;

        // ---- online softmax over this tile's 32 keys (row group = 8 lanes) ----
        float mt = fmaxf(fmaxf(sv0, sv1), fmaxf(sv2, sv3));
        mt = fmaxf(mt, __shfl_xor_sync(0xffffffffu, mt, 1));
        mt = fmaxf(mt, __shfl_xor_sync(0xffffffffu, mt, 2));
        mt = fmaxf(mt, __shfl_xor_sync(0xffffffffu, mt, 4));
        float mnew = fmaxf(m, mt);
        float corr = __expf(m - mnew);           // exp(-inf)=0 on first tile
        float p0 = __expf(sv0 - mnew);
        float p1 = __expf(sv1 - mnew);
        float p2 = __expf(sv2 - mnew);
        float p3 = __expf(sv3 - mnew);
        float psum = p0 + p1 + p2 + p3;
        psum += __shfl_xor_sync(0xffffffffu, psum, 1);
        psum += __shfl_xor_sync(0xffffffffu, psum, 2);
        psum += __shfl_xor_sync(0xffffffffu, psum, 4);
        l = l * corr + psum;
        m = mnew;

        // share probabilities across the row group
        Ps[q * 33 + s +  0] = p0;
        Ps[q * 33 + s +  8] = p1;
        Ps[q * 33 + s + 16] = p2;
        Ps[q * 33 + s + 24] = p3;

        // rescale accumulator
        #pragma unroll
        for (int j = 0; j < 32; ++j) { acc[j].x *= corr; acc[j].y *= corr; }

        __syncthreads();   // Ps visible to whole block

        // ---- PV: acc[q, d-slice] += sum_k p[q][k] * V[k][d-slice] ----
        #pragma unroll 4
        for (int k = 0; k < BK; ++k) {
            float pv = Ps[q * 33 + k];
            float2 p2v = make_float2(pv, pv);
            const float4* vrow = reinterpret_cast<const float4*>(cur + k * ROWF) + s;
            #pragma unroll
            for (int g = 0; g < 16; ++g) {
                float4 v4 = vrow[8 * g];          // interleaved slices: conflict-free
                acc[2 * g]     = ffma2(p2v, make_float2(v4.x, v4.y), acc[2 * g]);
                acc[2 * g + 1] = ffma2(p2v, make_float2(v4.z, v4.w), acc[2 * g + 1]);
            }
        }

        cp_wait0();        // next tile's data landed (had a whole compute phase)
        __syncthreads();   // all reads of cur/Ps done before next prefetch/overwrite
    }

    // ---- epilogue: out = acc / l  (+ previous pass if ACCUM) ----
    float invl = 1.0f / l;
    float* orow = Og + ((size_t)b * L_ + (size_t)qt * BQ + q) * D_;
    #pragma unroll
    for (int g = 0; g < 16; ++g) {
        int d4 = s + 8 * g;                       // interleaved float4 slice
        float4 o;
        o.x = acc[2 * g].x     * invl;
        o.y = acc[2 * g].y     * invl;
        o.z = acc[2 * g + 1].x * invl;
        o.w = acc[2 * g + 1].y * invl;
        float4* optr = reinterpret_cast<float4*>(orow + d4 * 4);
        if (ACCUM) {
            float4 prev = *optr;
            o.x += prev.x; o.y += prev.y; o.z += prev.z; o.w += prev.w;
        }
        *optr = o;
    }
}

extern "C" void kernel_launch(void* const* d_in, const int* in_sizes, int n_in,
                              void* d_out, int out_size)
{
    (void)in_sizes; (void)n_in; (void)out_size;
    const float* x1 = (const float*)d_in[0];
    const float* x2 = (const float*)d_in[1];
    float* out = (float*)d_out;

    const size_t SMEM = (size_t)(BQ * ROWF + 2 * BK * ROWF + BQ * 33) * sizeof(float); // 202368 B
    cudaFuncSetAttribute(mca_attn_kernel<false>, cudaFuncAttributeMaxDynamicSharedMemorySize, (int)SMEM);
    cudaFuncSetAttribute(mca_attn_kernel<true>,  cudaFuncAttributeMaxDynamicSharedMemorySize, (int)SMEM);

    dim3 grid(L_ / BQ, B_);
    // pass 1: out  = softmax_k(x1 x2^T / sqrt(d)) x2
    mca_attn_kernel<false><<<grid, NTH, SMEM>>>(x1, x2, out);
    // pass 2: out += softmax_q(x2 x1^T / sqrt(d)) x1   (transpose-softmax branch)
    mca_attn_kernel<true ><<<grid, NTH, SMEM>>>(x2, x1, out);
}

// round 13
// speedup vs baseline: 1.0002x; 1.0002x over previous
#include <cuda_runtime.h>
#include <math.h>

// Mutual cross attention, B=8, L=2048, D=512, fp32.
// out = attn(x1, x2, x2) + attn(x2, x1, x1)   (flash-style, two passes)

#define B_   8
#define L_   2048
#define D_   512
#define BQ   32            // query rows per block
#define BK   32            // key rows per tile
#define PADF 4             // row padding in floats (row = 2064 B, shifts banks by 16B/row)
#define ROWF (D_ + PADF)   // 516 floats per smem row
#define NTH  256
#define NKT  (L_ / BK)     // 64 key tiles

// ---------- packed f32x2 FMA (Blackwell FFMA2) ----------
__device__ __forceinline__ float2 ffma2(float2 a, float2 b, float2 c) {
    float2 d;
    asm("{\n\t"
        ".reg .b64 ra, rb, rc, rd;\n\t"
        "mov.b64 ra, {%2, %3};\n\t"
        "mov.b64 rb, {%4, %5};\n\t"
        "mov.b64 rc, {%6, %7};\n\t"
        "fma.rn.f32x2 rd, ra, rb, rc;\n\t"
        "mov.b64 {%0, %1}, rd;\n\t"
        "}"
        : "=f"(d.x), "=f"(d.y)
        : "f"(a.x), "f"(a.y), "f"(b.x), "f"(b.y), "f"(c.x), "f"(c.y));
    return d;
}

// ---------- cp.async helpers ----------
__device__ __forceinline__ void cp_async16(float* smem_dst, const float* gmem_src) {
    unsigned saddr = (unsigned)__cvta_generic_to_shared(smem_dst);
    asm volatile("cp.async.cg.shared.global [%0], [%1], 16;" :: "r"(saddr), "l"(gmem_src));
}
__device__ __forceinline__ void cp_commit() { asm volatile("cp.async.commit_group;"); }
__device__ __forceinline__ void cp_wait0()  { asm volatile("cp.async.wait_group 0;"); }

template <bool ACCUM>
__global__ void __launch_bounds__(NTH, 1)
mca_attn_kernel(const float* __restrict__ Qg,   // [B, L, D] queries
                const float* __restrict__ KVg,  // [B, L, D] keys == values
                float* __restrict__ Og)         // [B, L, D]
{
    extern __shared__ float smem[];
    float* Qs  = smem;                 // BQ * ROWF
    float* KV0 = Qs  + BQ * ROWF;      // BK * ROWF
    float* KV1 = KV0 + BK * ROWF;      // BK * ROWF
    float* Ps  = KV1 + BK * ROWF;      // BQ * 33 (probabilities tile)

    const int tid = threadIdx.x;
    const int qt  = blockIdx.x;        // query tile 0..63
    const int b   = blockIdx.y;        // batch
    const int q   = tid >> 3;          // local query row 0..31
    const int s   = tid & 7;           // 8-way split: k-groups for S, d-slices for PV

    const float scale = 0.04419417382415922f;  // 1/sqrt(512)

    const float* qbase = Qg  + ((size_t)b * L_ + (size_t)qt * BQ) * D_;
    const float* kbase = KVg + (size_t)b * L_ * D_;

    // --- async load Q tile + KV tile 0 (32 rows x 128 float4 each; 16 per thread) ---
    #pragma unroll
    for (int i = 0; i < 16; ++i) {
        int f  = tid + i * NTH;        // float4 index 0..4095
        int r  = f >> 7;
        int c4 = f & 127;
        cp_async16(Qs + r * ROWF + c4 * 4, qbase + r * D_ + c4 * 4);
    }
    #pragma unroll
    for (int i = 0; i < 16; ++i) {
        int f  = tid + i * NTH;
        int r  = f >> 7;
        int c4 = f & 127;
        cp_async16(KV0 + r * ROWF + c4 * 4, kbase + r * D_ + c4 * 4);
    }
    cp_commit();

    // accumulator: this thread owns query row q, interleaved d-slices d4 = s + 8g
    float2 acc[32];
    #pragma unroll
    for (int j = 0; j < 32; ++j) acc[j] = make_float2(0.f, 0.f);
    float m = -INFINITY;
    float l = 0.f;

    cp_wait0();
    __syncthreads();

    for (int kt = 0; kt < NKT; ++kt) {
        float* cur = (kt & 1) ? KV1 : KV0;
        float* nxt = (kt & 1) ? KV0 : KV1;

        // prefetch next KV tile into the buffer we finished with last iteration
        if (kt + 1 < NKT) {
            const float* g = kbase + (size_t)(kt + 1) * BK * D_;
            #pragma unroll
            for (int i = 0; i < 16; ++i) {
                int f  = tid + i * NTH;
                int r  = f >> 7;
                int c4 = f & 127;
                cp_async16(nxt + r * ROWF + c4 * 4, g + r * D_ + c4 * 4);
            }
            cp_commit();
        }

        // ---- S = Q . K^T on this tile: thread computes S[q][s + 8c], c = 0..3 ----
        float2 sa0 = make_float2(0.f, 0.f), sa1 = sa0, sa2 = sa0, sa3 = sa0;
        const float4* qrow = reinterpret_cast<const float4*>(Qs + q * ROWF);
        const float4* k0   = reinterpret_cast<const float4*>(cur + (s +  0) * ROWF);
        const float4* k1   = reinterpret_cast<const float4*>(cur + (s +  8) * ROWF);
        const float4* k2   = reinterpret_cast<const float4*>(cur + (s + 16) * ROWF);
        const float4* k3   = reinterpret_cast<const float4*>(cur + (s + 24) * ROWF);
        #pragma unroll 4
        for (int dq = 0; dq < D_ / 4; ++dq) {
            float4 qv = qrow[dq];
            float2 ql = make_float2(qv.x, qv.y);
            float2 qh = make_float2(qv.z, qv.w);
            float4 kv;
            kv = k0[dq];
            sa0 = ffma2(ql, make_float2(kv.x, kv.y), sa0);
            sa0 = ffma2(qh, make_float2(kv.z, kv.w), sa0);
            kv = k1[dq];
            sa1 = ffma2(ql, make_float2(kv.x, kv.y), sa1);
            sa1 = ffma2(qh, make_float2(kv.z, kv.w), sa1);
            kv = k2[dq];
            sa2 = ffma2(ql, make_float2(kv.x, kv.y), sa2);
            sa2 = ffma2(qh, make_float2(kv.z, kv.w), sa2);
            kv = k3[dq];
            sa3 = ffma2(ql, make_float2(kv.x, kv.y), sa3);
            sa3 = ffma2(qh, make_float2(kv.z, kv.w), sa3);
        }
        float sv0 = (sa0.x + sa0.y) * scale;
        float sv1 = (sa1.x + sa1.y) * scale;
        float sv2 = (sa2.x + sa2.y) * scale;
        float sv3 = (sa3.x + sa3.y) * scale;

        // ---- online softmax over this tile's 32 keys (row group = 8 lanes) ----
        float mt = fmaxf(fmaxf(sv0, sv1), fmaxf(sv2, sv3));
        mt = fmaxf(mt, __shfl_xor_sync(0xffffffffu, mt, 1));
        mt = fmaxf(mt, __shfl_xor_sync(0xffffffffu, mt, 2));
        mt = fmaxf(mt, __shfl_xor_sync(0xffffffffu, mt, 4));
        float mnew = fmaxf(m, mt);
        float corr = __expf(m - mnew);           // exp(-inf)=0 on first tile
        float p0 = __expf(sv0 - mnew);
        float p1 = __expf(sv1 - mnew);
        float p2 = __expf(sv2 - mnew);
        float p3 = __expf(sv3 - mnew);
        float psum = p0 + p1 + p2 + p3;
        psum += __shfl_xor_sync(0xffffffffu, psum, 1);
        psum += __shfl_xor_sync(0xffffffffu, psum, 2);
        psum += __shfl_xor_sync(0xffffffffu, psum, 4);
        l = l * corr + psum;
        m = mnew;

        // share probabilities across the row group
        Ps[q * 33 + s +  0] = p0;
        Ps[q * 33 + s +  8] = p1;
        Ps[q * 33 + s + 16] = p2;
        Ps[q * 33 + s + 24] = p3;

        // rescale accumulator
        #pragma unroll
        for (int j = 0; j < 32; ++j) { acc[j].x *= corr; acc[j].y *= corr; }

        __syncthreads();   // Ps visible to whole block

        // ---- PV: acc[q, d-slice] += sum_k p[q][k] * V[k][d-slice] ----
        #pragma unroll 4
        for (int k = 0; k < BK; ++k) {
            float pv = Ps[q * 33 + k];
            float2 p2v = make_float2(pv, pv);
            const float4* vrow = reinterpret_cast<const float4*>(cur + k * ROWF) + s;
            #pragma unroll
            for (int g = 0; g < 16; ++g) {
                float4 v4 = vrow[8 * g];          // interleaved slices: conflict-free
                acc[2 * g]     = ffma2(p2v, make_float2(v4.x, v4.y), acc[2 * g]);
                acc[2 * g + 1] = ffma2(p2v, make_float2(v4.z, v4.w), acc[2 * g + 1]);
            }
        }

        cp_wait0();        // next tile's data landed (had a whole compute phase)
        __syncthreads();   // all reads of cur/Ps done before next prefetch/overwrite
    }

    // ---- epilogue: out = acc / l  (+ previous pass if ACCUM) ----
    float invl = 1.0f / l;
    float* orow = Og + ((size_t)b * L_ + (size_t)qt * BQ + q) * D_;
    #pragma unroll
    for (int g = 0; g < 16; ++g) {
        int d4 = s + 8 * g;                       // interleaved float4 slice
        float4 o;
        o.x = acc[2 * g].x     * invl;
        o.y = acc[2 * g].y     * invl;
        o.z = acc[2 * g + 1].x * invl;
        o.w = acc[2 * g + 1].y * invl;
        float4* optr = reinterpret_cast<float4*>(orow + d4 * 4);
        if (ACCUM) {
            float4 prev = *optr;
            o.x += prev.x; o.y += prev.y; o.z += prev.z; o.w += prev.w;
        }
        *optr = o;
    }
}

extern "C" void kernel_launch(void* const* d_in, const int* in_sizes, int n_in,
                              void* d_out, int out_size)
{
    (void)in_sizes; (void)n_in; (void)out_size;
    const float* x1 = (const float*)d_in[0];
    const float* x2 = (const float*)d_in[1];
    float* out = (float*)d_out;

    const size_t SMEM = (size_t)(BQ * ROWF + 2 * BK * ROWF + BQ * 33) * sizeof(float); // 202368 B
    cudaFuncSetAttribute(mca_attn_kernel<false>, cudaFuncAttributeMaxDynamicSharedMemorySize, (int)SMEM);
    cudaFuncSetAttribute(mca_attn_kernel<true>,  cudaFuncAttributeMaxDynamicSharedMemorySize, (int)SMEM);

    dim3 grid(L_ / BQ, B_);
    // pass 1: out  = softmax_k(x1 x2^T / sqrt(d)) x2
    mca_attn_kernel<false><<<grid, NTH, SMEM>>>(x1, x2, out);
    // pass 2: out += softmax_q(x2 x1^T / sqrt(d)) x1   (transpose-softmax branch)
    mca_attn_kernel<true ><<<grid, NTH, SMEM>>>(x2, x1, out);
}

// round 14
// speedup vs baseline: 7.1700x; 7.1683x over previous
#include <cuda_runtime.h>
#include <cuda_bf16.h>
#include <math.h>

#define BB 8
#define LL 2048
#define DD 512

typedef __nv_bfloat16 bf;

// ---------------- device scratch (allowed: __device__ globals) ----------------
__device__ __align__(16) bf g_X1h[BB*LL*DD], g_X1l[BB*LL*DD];
__device__ __align__(16) bf g_X2h[BB*LL*DD], g_X2l[BB*LL*DD];
__device__ __align__(16) bf g_X1Th[BB*DD*LL], g_X1Tl[BB*DD*LL];
__device__ __align__(16) bf g_X2Th[BB*DD*LL], g_X2Tl[BB*DD*LL];
__device__ __align__(16) bf g_Eh[(size_t)BB*LL*LL], g_El[(size_t)BB*LL*LL];
__device__ float g_Zr[BB*LL], g_Zc[BB*LL];

// ---------------- helpers ----------------
__device__ __forceinline__ void split2(float v, bf& h, bf& l) {
    h = __float2bfloat16(v);
    l = __float2bfloat16(v - __bfloat162float(h));
}
__device__ __forceinline__ unsigned scvt(const void* p) {
    return (unsigned)__cvta_generic_to_shared(p);
}
__device__ __forceinline__ void cp_async16(void* dst, const void* src) {
    asm volatile("cp.async.cg.shared.global [%0], [%1], 16;" :: "r"(scvt(dst)), "l"(src));
}
__device__ __forceinline__ void cp_commit() { asm volatile("cp.async.commit_group;"); }
__device__ __forceinline__ void cp_wait1()  { asm volatile("cp.async.wait_group 1;"); }
__device__ __forceinline__ void cp_wait0()  { asm volatile("cp.async.wait_group 0;"); }

__device__ __forceinline__ void ldsm4(unsigned* r, unsigned a) {
    asm volatile("ldmatrix.sync.aligned.m8n8.x4.shared.b16 {%0,%1,%2,%3},[%4];"
        : "=r"(r[0]), "=r"(r[1]), "=r"(r[2]), "=r"(r[3]) : "r"(a));
}
__device__ __forceinline__ void ldsm4t(unsigned* r, unsigned a) {
    asm volatile("ldmatrix.sync.aligned.m8n8.x4.trans.shared.b16 {%0,%1,%2,%3},[%4];"
        : "=r"(r[0]), "=r"(r[1]), "=r"(r[2]), "=r"(r[3]) : "r"(a));
}
__device__ __forceinline__ void mma16816(float* c, const unsigned* a, const unsigned* b) {
    asm volatile("mma.sync.aligned.m16n8k16.row.col.f32.bf16.bf16.f32 "
        "{%0,%1,%2,%3}, {%4,%5,%6,%7}, {%8,%9}, {%0,%1,%2,%3};"
        : "+f"(c[0]), "+f"(c[1]), "+f"(c[2]), "+f"(c[3])
        : "r"(a[0]), "r"(a[1]), "r"(a[2]), "r"(a[3]), "r"(b[0]), "r"(b[1]));
}

// ---------------- prep: split + transpose both inputs ----------------
// grid (LL/32, DD/32, 2*BB), block (32, 8)
__global__ void prep_kern(const float* __restrict__ x1, const float* __restrict__ x2) {
    __shared__ float tile[32][33];
    int b = blockIdx.z >> 1, which = blockIdx.z & 1;
    const float* src = which ? x2 : x1;
    bf* Rh = which ? g_X2h : g_X1h;   bf* Rl = which ? g_X2l : g_X1l;
    bf* Th = which ? g_X2Th : g_X1Th; bf* Tl = which ? g_X2Tl : g_X1Tl;
    int l0 = blockIdx.x * 32, d0 = blockIdx.y * 32;
    int lx = threadIdx.x, ty = threadIdx.y;
    #pragma unroll
    for (int i = 0; i < 4; ++i) {
        int l = l0 + ty + i * 8;
        float v = src[((size_t)b * LL + l) * DD + d0 + lx];
        tile[ty + i * 8][lx] = v;
        bf h, lo; split2(v, h, lo);
        size_t o = ((size_t)b * LL + l) * DD + d0 + lx;
        Rh[o] = h; Rl[o] = lo;
    }
    __syncthreads();
    #pragma unroll
    for (int i = 0; i < 4; ++i) {
        int d = d0 + ty + i * 8;
        float v = tile[lx][ty + i * 8];
        bf h, lo; split2(v, h, lo);
        size_t o = ((size_t)b * DD + d) * LL + l0 + lx;
        Th[o] = h; Tl[o] = lo;
    }
}

// ---------------- zero Zc ----------------
__global__ void zero_kern() {
    int i = blockIdx.x * 256 + threadIdx.x;
    if (i < BB * LL) g_Zc[i] = 0.f;
}

// ---------------- row sums of E ----------------  grid (LL, BB), 256 thr
__global__ void rowsum_kern() {
    int q = blockIdx.x, b = blockIdx.y, t = threadIdx.x;
    size_t base = ((size_t)b * LL + q) * LL;
    float s = 0.f;
    for (int k = t; k < LL; k += 256)
        s += __bfloat162float(g_Eh[base + k]) + __bfloat162float(g_El[base + k]);
    #pragma unroll
    for (int o = 16; o; o >>= 1) s += __shfl_xor_sync(0xffffffffu, s, o);
    __shared__ float red[8];
    if ((t & 31) == 0) red[t >> 5] = s;
    __syncthreads();
    if (t == 0) {
        float tot = 0.f;
        #pragma unroll
        for (int w = 0; w < 8; ++w) tot += red[w];
        g_Zr[b * LL + q] = tot;
    }
}

// ---------------- col sums of E ----------------  grid (8, 32, BB), 256 thr
__global__ void colsum_kern() {
    int b = blockIdx.z;
    int k = blockIdx.x * 256 + threadIdx.x;
    int q0 = blockIdx.y * 64;
    size_t base = (size_t)b * LL * LL + k;
    float s = 0.f;
    #pragma unroll 4
    for (int j = 0; j < 64; ++j) {
        size_t o = base + (size_t)(q0 + j) * LL;
        s += __bfloat162float(g_Eh[o]) + __bfloat162float(g_El[o]);
    }
    atomicAdd(&g_Zc[b * LL + k], s);
}

// ---------------- unified GEMM kernel ----------------
// MODE 0: E = exp(scale * X1 X2^T), split-written to Eh/El.   M=N=LL, K=DD x3
// MODE 1: out  = diag(1/Zr) * E * x2      (B = X2T)           M=LL, N=DD, K=LL x3
// MODE 2: out += diag(1/Zc) * E^T * x1    (A = E via ldsm.trans, B = X1T)
template <int MODE>
__global__ void __launch_bounds__(256)
gemm_kern(float* __restrict__ Out)
{
    constexpr int KP  = (MODE == 0) ? DD : LL;   // K per phase
    constexpr int NKC = KP / 64;                 // chunks per phase
    constexpr int NCH = 3 * NKC;
    constexpr int LDA = (MODE == 0) ? DD : LL;
    constexpr int LDB = (MODE == 0) ? DD : LL;
    constexpr int PA = 72, PA2 = 136, PB = 72;
    constexpr int ASZ = (MODE == 2) ? 64 * PA2 : 128 * PA;

    extern __shared__ bf sm[];
    bf* Asm = sm;                  // 2 buffers of ASZ
    bf* Bsm = sm + 2 * ASZ;        // 2 buffers of 128*PB

    const int t = threadIdx.x, lane = t & 31, warp = t >> 5;
    const int wm = warp >> 2, wn = warp & 3;
    const int bN = blockIdx.x, bM = blockIdx.y, b = blockIdx.z;
    const int m0 = bM * 128, n0 = bN * 128;

    const size_t ab = (MODE == 0) ? (size_t)b * LL * DD : (size_t)b * LL * LL;
    const size_t bb = (MODE == 0) ? (size_t)b * LL * DD : (size_t)b * DD * LL;
    const bf* Ap[3]; const bf* Bp[3];
    if (MODE == 0) {
        Ap[0] = g_X1h + ab; Ap[1] = g_X1l + ab; Ap[2] = g_X1h + ab;
        Bp[0] = g_X2h + bb; Bp[1] = g_X2h + bb; Bp[2] = g_X2l + bb;
    } else if (MODE == 1) {
        Ap[0] = g_Eh + ab;  Ap[1] = g_El + ab;  Ap[2] = g_Eh + ab;
        Bp[0] = g_X2Th + bb; Bp[1] = g_X2Th + bb; Bp[2] = g_X2Tl + bb;
    } else {
        Ap[0] = g_Eh + ab;  Ap[1] = g_El + ab;  Ap[2] = g_Eh + ab;
        Bp[0] = g_X1Th + bb; Bp[1] = g_X1Th + bb; Bp[2] = g_X1Tl + bb;
    }

    float acc[4][4][4];
    #pragma unroll
    for (int j = 0; j < 4; ++j)
        #pragma unroll
        for (int n = 0; n < 4; ++n)
            #pragma unroll
            for (int i = 0; i < 4; ++i) acc[j][n][i] = 0.f;

    auto loadA = [&](int c, int buf) {
        const bf* src = Ap[c / NKC];
        int k0 = (c % NKC) * 64;
        if (MODE == 2) {
            #pragma unroll
            for (int i = 0; i < 4; ++i) {
                int idx = t + i * 256, r = idx >> 4, s8 = idx & 15;
                cp_async16(Asm + buf * ASZ + r * PA2 + s8 * 8,
                           src + (size_t)(k0 + r) * LDA + m0 + s8 * 8);
            }
        } else {
            #pragma unroll
            for (int i = 0; i < 4; ++i) {
                int idx = t + i * 256, r = idx >> 3, s8 = idx & 7;
                cp_async16(Asm + buf * ASZ + r * PA + s8 * 8,
                           src + (size_t)(m0 + r) * LDA + k0 + s8 * 8);
            }
        }
    };
    auto loadB = [&](int c, int buf) {
        const bf* src = Bp[c / NKC];
        int k0 = (c % NKC) * 64;
        #pragma unroll
        for (int i = 0; i < 4; ++i) {
            int idx = t + i * 256, r = idx >> 3, s8 = idx & 7;
            cp_async16(Bsm + buf * (128 * PB) + r * PB + s8 * 8,
                       src + (size_t)(n0 + r) * LDB + k0 + s8 * 8);
        }
    };
    auto comp = [&](int buf) {
        const bf* At = Asm + buf * ASZ;
        const bf* Bt = Bsm + buf * (128 * PB);
        #pragma unroll
        for (int k16 = 0; k16 < 4; ++k16) {
            unsigned bfr[4][2];
            #pragma unroll
            for (int nb = 0; nb < 2; ++nb) {
                unsigned r[4];
                ldsm4(r, scvt(Bt + (wn * 32 + nb * 16 + (lane & 15)) * PB
                                 + k16 * 16 + (lane >> 4) * 8));
                bfr[nb * 2 + 0][0] = r[0]; bfr[nb * 2 + 0][1] = r[2];
                bfr[nb * 2 + 1][0] = r[1]; bfr[nb * 2 + 1][1] = r[3];
            }
            unsigned afr[4][4];
            #pragma unroll
            for (int j = 0; j < 4; ++j) {
                if (MODE == 2) {
                    ldsm4t(afr[j], scvt(At + (k16 * 16 + (lane & 7) + ((lane >> 4) & 1) * 8) * PA2
                                           + wm * 64 + j * 16 + ((lane >> 3) & 1) * 8));
                } else {
                    ldsm4(afr[j], scvt(At + (wm * 64 + j * 16 + (lane & 15)) * PA
                                          + k16 * 16 + (lane >> 4) * 8));
                }
            }
            #pragma unroll
            for (int j = 0; j < 4; ++j)
                #pragma unroll
                for (int n = 0; n < 4; ++n)
                    mma16816(acc[j][n], afr[j], bfr[n]);
        }
    };

    loadA(0, 0); loadB(0, 0); cp_commit();
    for (int c = 0; c < NCH; ++c) {
        if (c + 1 < NCH) { loadA(c + 1, (c + 1) & 1); loadB(c + 1, (c + 1) & 1); cp_commit(); cp_wait1(); }
        else cp_wait0();
        __syncthreads();
        comp(c & 1);
        __syncthreads();
    }

    // ---------------- epilogue ----------------
    const float scale = 0.044194173824159216f;
    #pragma unroll
    for (int j = 0; j < 4; ++j) {
        int r0 = m0 + wm * 64 + j * 16 + (lane >> 2);
        if (MODE == 0) {
            #pragma unroll
            for (int jn = 0; jn < 4; ++jn) {
                int cc = n0 + wn * 32 + jn * 8 + 2 * (lane & 3);
                float* a = acc[j][jn];
                #pragma unroll
                for (int h = 0; h < 2; ++h) {   // h=0: row r0, h=1: row r0+8
                    int rr = r0 + h * 8;
                    float e0 = __expf(scale * a[2 * h + 0]);
                    float e1 = __expf(scale * a[2 * h + 1]);
                    bf h0, l0, h1, l1; split2(e0, h0, l0); split2(e1, h1, l1);
                    size_t o = ((size_t)b * LL + rr) * LL + cc;
                    *(unsigned*)&g_Eh[o] = (unsigned)__bfloat16_as_ushort(h0)
                                         | ((unsigned)__bfloat16_as_ushort(h1) << 16);
                    *(unsigned*)&g_El[o] = (unsigned)__bfloat16_as_ushort(l0)
                                         | ((unsigned)__bfloat16_as_ushort(l1) << 16);
                }
            }
        } else {
            const float* Zs = (MODE == 1) ? g_Zr : g_Zc;
            float f0 = __frcp_rn(Zs[b * LL + r0]);
            float f1 = __frcp_rn(Zs[b * LL + r0 + 8]);
            #pragma unroll
            for (int jn = 0; jn < 4; ++jn) {
                int cc = n0 + wn * 32 + jn * 8 + 2 * (lane & 3);
                float* a = acc[j][jn];
                float2* p0 = (float2*)(Out + ((size_t)b * LL + r0) * DD + cc);
                float2* p1 = (float2*)(Out + ((size_t)b * LL + r0 + 8) * DD + cc);
                if (MODE == 1) {
                    *p0 = make_float2(a[0] * f0, a[1] * f0);
                    *p1 = make_float2(a[2] * f1, a[3] * f1);
                } else {
                    float2 v0 = *p0; v0.x += a[0] * f0; v0.y += a[1] * f0; *p0 = v0;
                    float2 v1 = *p1; v1.x += a[2] * f1; v1.y += a[3] * f1; *p1 = v1;
                }
            }
        }
    }
}

// ---------------- launch ----------------
extern "C" void kernel_launch(void* const* d_in, const int* in_sizes, int n_in,
                              void* d_out, int out_size)
{
    (void)in_sizes; (void)n_in; (void)out_size;
    const float* x1 = (const float*)d_in[0];
    const float* x2 = (const float*)d_in[1];
    float* out = (float*)d_out;

    const int SM01 = (2 * 128 * 72 + 2 * 128 * 72) * 2;   // 73728 B
    const int SM2  = (2 * 64 * 136 + 2 * 128 * 72) * 2;   // 71680 B
    cudaFuncSetAttribute(gemm_kern<0>, cudaFuncAttributeMaxDynamicSharedMemorySize, SM01);
    cudaFuncSetAttribute(gemm_kern<1>, cudaFuncAttributeMaxDynamicSharedMemorySize, SM01);
    cudaFuncSetAttribute(gemm_kern<2>, cudaFuncAttributeMaxDynamicSharedMemorySize, SM2);

    zero_kern<<<64, 256>>>();
    prep_kern<<<dim3(LL / 32, DD / 32, 2 * BB), dim3(32, 8)>>>(x1, x2);
    gemm_kern<0><<<dim3(LL / 128, LL / 128, BB), 256, SM01>>>(nullptr);  // E = exp(scale*S)
    rowsum_kern<<<dim3(LL, BB), 256>>>();
    colsum_kern<<<dim3(8, 32, BB), 256>>>();
    gemm_kern<1><<<dim3(DD / 128, LL / 128, BB), 256, SM01>>>(out);      // out  = P  x2
    gemm_kern<2><<<dim3(DD / 128, LL / 128, BB), 256, SM2 >>>(out);      // out += Pc x1
}

// round 15
// speedup vs baseline: 9.4351x; 1.3159x over previous
#include <cuda_runtime.h>
#include <cuda_fp16.h>
#include <math.h>

#define BB 8
#define LL 2048
#define DD 512

typedef __half hf;

// ---------------- device scratch ----------------
__device__ __align__(16) hf g_X1h[BB*LL*DD], g_X1l[BB*LL*DD];
__device__ __align__(16) hf g_X2h[BB*LL*DD], g_X2l[BB*LL*DD];
__device__ __align__(16) hf g_X1Th[BB*DD*LL], g_X1Tl[BB*DD*LL];
__device__ __align__(16) hf g_X2Th[BB*DD*LL], g_X2Tl[BB*DD*LL];
__device__ __align__(16) hf g_E[(size_t)BB*LL*LL];          // 67 MB, fp16 exp(S)
__device__ float g_Zr[BB*LL], g_Zc[BB*LL];

// ---------------- helpers ----------------
__device__ __forceinline__ void split2(float v, hf& h, hf& l) {
    h = __float2half_rn(v);
    l = __float2half_rn(v - __half2float(h));
}
__device__ __forceinline__ unsigned scvt(const void* p) {
    return (unsigned)__cvta_generic_to_shared(p);
}
__device__ __forceinline__ void cp_async16(void* dst, const void* src) {
    asm volatile("cp.async.cg.shared.global [%0], [%1], 16;" :: "r"(scvt(dst)), "l"(src));
}
__device__ __forceinline__ void cp_commit() { asm volatile("cp.async.commit_group;"); }
__device__ __forceinline__ void cp_wait1()  { asm volatile("cp.async.wait_group 1;"); }
__device__ __forceinline__ void cp_wait0()  { asm volatile("cp.async.wait_group 0;"); }

__device__ __forceinline__ void ldsm4(unsigned* r, unsigned a) {
    asm volatile("ldmatrix.sync.aligned.m8n8.x4.shared.b16 {%0,%1,%2,%3},[%4];"
        : "=r"(r[0]), "=r"(r[1]), "=r"(r[2]), "=r"(r[3]) : "r"(a));
}
__device__ __forceinline__ void ldsm4t(unsigned* r, unsigned a) {
    asm volatile("ldmatrix.sync.aligned.m8n8.x4.trans.shared.b16 {%0,%1,%2,%3},[%4];"
        : "=r"(r[0]), "=r"(r[1]), "=r"(r[2]), "=r"(r[3]) : "r"(a));
}
__device__ __forceinline__ void mma16816(float* c, const unsigned* a, const unsigned* b) {
    asm volatile("mma.sync.aligned.m16n8k16.row.col.f32.f16.f16.f32 "
        "{%0,%1,%2,%3}, {%4,%5,%6,%7}, {%8,%9}, {%0,%1,%2,%3};"
        : "+f"(c[0]), "+f"(c[1]), "+f"(c[2]), "+f"(c[3])
        : "r"(a[0]), "r"(a[1]), "r"(a[2]), "r"(a[3]), "r"(b[0]), "r"(b[1]));
}

// ---------------- prep: split + transpose both inputs ----------------
// grid (LL/32, DD/32, 2*BB), block (32, 8)
__global__ void prep_kern(const float* __restrict__ x1, const float* __restrict__ x2) {
    __shared__ float tile[32][33];
    int b = blockIdx.z >> 1, which = blockIdx.z & 1;
    const float* src = which ? x2 : x1;
    hf* Rh = which ? g_X2h : g_X1h;   hf* Rl = which ? g_X2l : g_X1l;
    hf* Th = which ? g_X2Th : g_X1Th; hf* Tl = which ? g_X2Tl : g_X1Tl;
    int l0 = blockIdx.x * 32, d0 = blockIdx.y * 32;
    int lx = threadIdx.x, ty = threadIdx.y;
    #pragma unroll
    for (int i = 0; i < 4; ++i) {
        int l = l0 + ty + i * 8;
        float v = src[((size_t)b * LL + l) * DD + d0 + lx];
        tile[ty + i * 8][lx] = v;
        hf h, lo; split2(v, h, lo);
        size_t o = ((size_t)b * LL + l) * DD + d0 + lx;
        Rh[o] = h; Rl[o] = lo;
    }
    __syncthreads();
    #pragma unroll
    for (int i = 0; i < 4; ++i) {
        int d = d0 + ty + i * 8;
        float v = tile[lx][ty + i * 8];
        hf h, lo; split2(v, h, lo);
        size_t o = ((size_t)b * DD + d) * LL + l0 + lx;
        Th[o] = h; Tl[o] = lo;
    }
}

// ---------------- zero both Z arrays ----------------
__global__ void zero_kern() {
    int i = blockIdx.x * 256 + threadIdx.x;
    if (i < BB * LL) { g_Zr[i] = 0.f; g_Zc[i] = 0.f; }
}

// ---------------- unified GEMM kernel ----------------
// MODE 0: E = exp(scale * X1 X2^T) -> fp16; row/col sums fused via atomics.
// MODE 1: out  = diag(1/Zr) * E * x2      (B = X2T splits, 2 phases)
// MODE 2: out += diag(1/Zc) * E^T * x1    (A = E via ldsm.trans, 2 phases)
template <int MODE>
__global__ void __launch_bounds__(256)
gemm_kern(float* __restrict__ Out)
{
    constexpr int KP  = (MODE == 0) ? DD : LL;
    constexpr int NKC = KP / 64;
    constexpr int NPH = (MODE == 0) ? 3 : 2;
    constexpr int NCH = NPH * NKC;
    constexpr int LDA = (MODE == 0) ? DD : LL;
    constexpr int LDB = (MODE == 0) ? DD : LL;
    constexpr int PA = 72, PA2 = 136, PB = 72;
    constexpr int ASZ = (MODE == 2) ? 64 * PA2 : 128 * PA;

    extern __shared__ hf sm[];
    hf* Asm = sm;
    hf* Bsm = sm + 2 * ASZ;
    __shared__ float sZr[128], sZc[128];

    const int t = threadIdx.x, lane = t & 31, warp = t >> 5;
    const int wm = warp >> 2, wn = warp & 3;
    const int bN = blockIdx.x, bM = blockIdx.y, b = blockIdx.z;
    const int m0 = bM * 128, n0 = bN * 128;

    if (MODE == 0 && t < 128) { sZr[t] = 0.f; sZc[t] = 0.f; }

    const size_t ab = (MODE == 0) ? (size_t)b * LL * DD : (size_t)b * LL * LL;
    const size_t bb = (MODE == 0) ? (size_t)b * LL * DD : (size_t)b * DD * LL;
    const hf* Ap[3]; const hf* Bp[3];
    if (MODE == 0) {
        Ap[0] = g_X1h + ab; Ap[1] = g_X1l + ab; Ap[2] = g_X1h + ab;
        Bp[0] = g_X2h + bb; Bp[1] = g_X2h + bb; Bp[2] = g_X2l + bb;
    } else if (MODE == 1) {
        Ap[0] = g_E + ab;  Ap[1] = g_E + ab;  Ap[2] = nullptr;
        Bp[0] = g_X2Th + bb; Bp[1] = g_X2Tl + bb; Bp[2] = nullptr;
    } else {
        Ap[0] = g_E + ab;  Ap[1] = g_E + ab;  Ap[2] = nullptr;
        Bp[0] = g_X1Th + bb; Bp[1] = g_X1Tl + bb; Bp[2] = nullptr;
    }

    float acc[4][4][4];
    #pragma unroll
    for (int j = 0; j < 4; ++j)
        #pragma unroll
        for (int n = 0; n < 4; ++n)
            #pragma unroll
            for (int i = 0; i < 4; ++i) acc[j][n][i] = 0.f;

    auto loadA = [&](int c, int buf) {
        const hf* src = Ap[c / NKC];
        int k0 = (c % NKC) * 64;
        if (MODE == 2) {
            #pragma unroll
            for (int i = 0; i < 4; ++i) {
                int idx = t + i * 256, r = idx >> 4, s8 = idx & 15;
                cp_async16(Asm + buf * ASZ + r * PA2 + s8 * 8,
                           src + (size_t)(k0 + r) * LDA + m0 + s8 * 8);
            }
        } else {
            #pragma unroll
            for (int i = 0; i < 4; ++i) {
                int idx = t + i * 256, r = idx >> 3, s8 = idx & 7;
                cp_async16(Asm + buf * ASZ + r * PA + s8 * 8,
                           src + (size_t)(m0 + r) * LDA + k0 + s8 * 8);
            }
        }
    };
    auto loadB = [&](int c, int buf) {
        const hf* src = Bp[c / NKC];
        int k0 = (c % NKC) * 64;
        #pragma unroll
        for (int i = 0; i < 4; ++i) {
            int idx = t + i * 256, r = idx >> 3, s8 = idx & 7;
            cp_async16(Bsm + buf * (128 * PB) + r * PB + s8 * 8,
                       src + (size_t)(n0 + r) * LDB + k0 + s8 * 8);
        }
    };
    auto comp = [&](int buf) {
        const hf* At = Asm + buf * ASZ;
        const hf* Bt = Bsm + buf * (128 * PB);
        #pragma unroll
        for (int k16 = 0; k16 < 4; ++k16) {
            unsigned bfr[4][2];
            #pragma unroll
            for (int nb = 0; nb < 2; ++nb) {
                unsigned r[4];
                ldsm4(r, scvt(Bt + (wn * 32 + nb * 16 + (lane & 15)) * PB
                                 + k16 * 16 + (lane >> 4) * 8));
                bfr[nb * 2 + 0][0] = r[0]; bfr[nb * 2 + 0][1] = r[2];
                bfr[nb * 2 + 1][0] = r[1]; bfr[nb * 2 + 1][1] = r[3];
            }
            unsigned afr[4][4];
            #pragma unroll
            for (int j = 0; j < 4; ++j) {
                if (MODE == 2) {
                    ldsm4t(afr[j], scvt(At + (k16 * 16 + (lane & 7) + ((lane >> 4) & 1) * 8) * PA2
                                           + wm * 64 + j * 16 + ((lane >> 3) & 1) * 8));
                } else {
                    ldsm4(afr[j], scvt(At + (wm * 64 + j * 16 + (lane & 15)) * PA
                                          + k16 * 16 + (lane >> 4) * 8));
                }
            }
            #pragma unroll
            for (int j = 0; j < 4; ++j)
                #pragma unroll
                for (int n = 0; n < 4; ++n)
                    mma16816(acc[j][n], afr[j], bfr[n]);
        }
    };

    loadA(0, 0); loadB(0, 0); cp_commit();
    for (int c = 0; c < NCH; ++c) {
        if (c + 1 < NCH) { loadA(c + 1, (c + 1) & 1); loadB(c + 1, (c + 1) & 1); cp_commit(); cp_wait1(); }
        else cp_wait0();
        __syncthreads();
        comp(c & 1);
        __syncthreads();
    }

    // ---------------- epilogue ----------------
    const float scale = 0.044194173824159216f;
    if (MODE == 0) {
        float cp[4][2];
        #pragma unroll
        for (int jn = 0; jn < 4; ++jn) { cp[jn][0] = 0.f; cp[jn][1] = 0.f; }
        #pragma unroll
        for (int j = 0; j < 4; ++j) {
            int rloc = wm * 64 + j * 16 + (lane >> 2);
            int rglob = m0 + rloc;
            float rp0 = 0.f, rp1 = 0.f;
            #pragma unroll
            for (int jn = 0; jn < 4; ++jn) {
                int cc = n0 + wn * 32 + jn * 8 + 2 * (lane & 3);
                float* a = acc[j][jn];
                hf h00 = __float2half_rn(__expf(scale * a[0]));
                hf h01 = __float2half_rn(__expf(scale * a[1]));
                hf h10 = __float2half_rn(__expf(scale * a[2]));
                hf h11 = __float2half_rn(__expf(scale * a[3]));
                size_t o0 = ((size_t)b * LL + rglob) * LL + cc;
                size_t o1 = ((size_t)b * LL + rglob + 8) * LL + cc;
                *(__half2*)&g_E[o0] = __halves2half2(h00, h01);
                *(__half2*)&g_E[o1] = __halves2half2(h10, h11);
                float v00 = __half2float(h00), v01 = __half2float(h01);
                float v10 = __half2float(h10), v11 = __half2float(h11);
                rp0 += v00 + v01;  rp1 += v10 + v11;
                cp[jn][0] += v00 + v10;  cp[jn][1] += v01 + v11;
            }
            rp0 += __shfl_xor_sync(0xffffffffu, rp0, 1);
            rp0 += __shfl_xor_sync(0xffffffffu, rp0, 2);
            rp1 += __shfl_xor_sync(0xffffffffu, rp1, 1);
            rp1 += __shfl_xor_sync(0xffffffffu, rp1, 2);
            if ((lane & 3) == 0) {
                atomicAdd(&sZr[rloc], rp0);
                atomicAdd(&sZr[rloc + 8], rp1);
            }
        }
        #pragma unroll
        for (int jn = 0; jn < 4; ++jn)
            #pragma unroll
            for (int i = 0; i < 2; ++i) {
                float v = cp[jn][i];
                v += __shfl_xor_sync(0xffffffffu, v, 4);
                v += __shfl_xor_sync(0xffffffffu, v, 8);
                v += __shfl_xor_sync(0xffffffffu, v, 16);
                if (lane < 4)
                    atomicAdd(&sZc[wn * 32 + jn * 8 + 2 * lane + i], v);
            }
        __syncthreads();
        if (t < 128) {
            atomicAdd(&g_Zr[b * LL + m0 + t], sZr[t]);
            atomicAdd(&g_Zc[b * LL + n0 + t], sZc[t]);
        }
    } else {
        const float* Zs = (MODE == 1) ? g_Zr : g_Zc;
        #pragma unroll
        for (int j = 0; j < 4; ++j) {
            int r0 = m0 + wm * 64 + j * 16 + (lane >> 2);
            float f0 = __frcp_rn(Zs[b * LL + r0]);
            float f1 = __frcp_rn(Zs[b * LL + r0 + 8]);
            #pragma unroll
            for (int jn = 0; jn < 4; ++jn) {
                int cc = n0 + wn * 32 + jn * 8 + 2 * (lane & 3);
                float* a = acc[j][jn];
                float2* p0 = (float2*)(Out + ((size_t)b * LL + r0) * DD + cc);
                float2* p1 = (float2*)(Out + ((size_t)b * LL + r0 + 8) * DD + cc);
                if (MODE == 1) {
                    *p0 = make_float2(a[0] * f0, a[1] * f0);
                    *p1 = make_float2(a[2] * f1, a[3] * f1);
                } else {
                    float2 v0 = *p0; v0.x += a[0] * f0; v0.y += a[1] * f0; *p0 = v0;
                    float2 v1 = *p1; v1.x += a[2] * f1; v1.y += a[3] * f1; *p1 = v1;
                }
            }
        }
    }
}

// ---------------- launch ----------------
extern "C" void kernel_launch(void* const* d_in, const int* in_sizes, int n_in,
                              void* d_out, int out_size)
{
    (void)in_sizes; (void)n_in; (void)out_size;
    const float* x1 = (const float*)d_in[0];
    const float* x2 = (const float*)d_in[1];
    float* out = (float*)d_out;

    const int SM01 = (2 * 128 * 72 + 2 * 128 * 72) * 2;   // 73728 B
    const int SM2  = (2 * 64 * 136 + 2 * 128 * 72) * 2;   // 71680 B
    cudaFuncSetAttribute(gemm_kern<0>, cudaFuncAttributeMaxDynamicSharedMemorySize, SM01);
    cudaFuncSetAttribute(gemm_kern<1>, cudaFuncAttributeMaxDynamicSharedMemorySize, SM01);
    cudaFuncSetAttribute(gemm_kern<2>, cudaFuncAttributeMaxDynamicSharedMemorySize, SM2);

    zero_kern<<<64, 256>>>();
    prep_kern<<<dim3(LL / 32, DD / 32, 2 * BB), dim3(32, 8)>>>(x1, x2);
    gemm_kern<0><<<dim3(LL / 128, LL / 128, BB), 256, SM01>>>(nullptr);  // E + fused Zr/Zc
    gemm_kern<1><<<dim3(DD / 128, LL / 128, BB), 256, SM01>>>(out);      // out  = P  x2
    gemm_kern<2><<<dim3(DD / 128, LL / 128, BB), 256, SM2 >>>(out);      // out += Pc x1
}

// round 16
// speedup vs baseline: 11.5071x; 1.2196x over previous
#include <cuda_runtime.h>
#include <cuda_fp16.h>
#include <math.h>

#define BB 8
#define LL 2048
#define DD 512

typedef __half hf;

// ---------------- device scratch ----------------
__device__ __align__(16) hf g_X1h[BB*LL*DD], g_X1l[BB*LL*DD];
__device__ __align__(16) hf g_X2h[BB*LL*DD];
__device__ __align__(16) hf g_X1Th[BB*DD*LL], g_X1Tl[BB*DD*LL];
__device__ __align__(16) hf g_X2Th[BB*DD*LL], g_X2Tl[BB*DD*LL];
__device__ __align__(16) hf g_E[(size_t)BB*LL*LL];          // 67 MB, fp16 exp(S)
__device__ float g_Zr[BB*LL], g_Zc[BB*LL];

// ---------------- helpers ----------------
__device__ __forceinline__ void split2(float v, hf& h, hf& l) {
    h = __float2half_rn(v);
    l = __float2half_rn(v - __half2float(h));
}
__device__ __forceinline__ unsigned scvt(const void* p) {
    return (unsigned)__cvta_generic_to_shared(p);
}
__device__ __forceinline__ void cp_async16(void* dst, const void* src) {
    asm volatile("cp.async.cg.shared.global [%0], [%1], 16;" :: "r"(scvt(dst)), "l"(src));
}
__device__ __forceinline__ void cp_commit() { asm volatile("cp.async.commit_group;"); }
__device__ __forceinline__ void cp_wait1()  { asm volatile("cp.async.wait_group 1;"); }
__device__ __forceinline__ void cp_wait0()  { asm volatile("cp.async.wait_group 0;"); }

__device__ __forceinline__ void ldsm4(unsigned* r, unsigned a) {
    asm volatile("ldmatrix.sync.aligned.m8n8.x4.shared.b16 {%0,%1,%2,%3},[%4];"
        : "=r"(r[0]), "=r"(r[1]), "=r"(r[2]), "=r"(r[3]) : "r"(a));
}
__device__ __forceinline__ void ldsm4t(unsigned* r, unsigned a) {
    asm volatile("ldmatrix.sync.aligned.m8n8.x4.trans.shared.b16 {%0,%1,%2,%3},[%4];"
        : "=r"(r[0]), "=r"(r[1]), "=r"(r[2]), "=r"(r[3]) : "r"(a));
}
__device__ __forceinline__ void mma16816(float* c, const unsigned* a, const unsigned* b) {
    asm volatile("mma.sync.aligned.m16n8k16.row.col.f32.f16.f16.f32 "
        "{%0,%1,%2,%3}, {%4,%5,%6,%7}, {%8,%9}, {%0,%1,%2,%3};"
        : "+f"(c[0]), "+f"(c[1]), "+f"(c[2]), "+f"(c[3])
        : "r"(a[0]), "r"(a[1]), "r"(a[2]), "r"(a[3]), "r"(b[0]), "r"(b[1]));
}

// ---------------- prep: split + transpose both inputs ----------------
// grid (LL/32, DD/32, 2*BB), block (32, 8)
__global__ void prep_kern(const float* __restrict__ x1, const float* __restrict__ x2) {
    __shared__ float tile[32][33];
    int b = blockIdx.z >> 1, which = blockIdx.z & 1;
    const float* src = which ? x2 : x1;
    int l0 = blockIdx.x * 32, d0 = blockIdx.y * 32;
    int lx = threadIdx.x, ty = threadIdx.y;
    #pragma unroll
    for (int i = 0; i < 4; ++i) {
        int l = l0 + ty + i * 8;
        float v = src[((size_t)b * LL + l) * DD + d0 + lx];
        tile[ty + i * 8][lx] = v;
        hf h, lo; split2(v, h, lo);
        size_t o = ((size_t)b * LL + l) * DD + d0 + lx;
        if (which) { g_X2h[o] = h; }
        else       { g_X1h[o] = h; g_X1l[o] = lo; }
    }
    __syncthreads();
    #pragma unroll
    for (int i = 0; i < 4; ++i) {
        int d = d0 + ty + i * 8;
        float v = tile[lx][ty + i * 8];
        hf h, lo; split2(v, h, lo);
        size_t o = ((size_t)b * DD + d) * LL + l0 + lx;
        if (which) { g_X2Th[o] = h; g_X2Tl[o] = lo; }
        else       { g_X1Th[o] = h; g_X1Tl[o] = lo; }
    }
}

// ---------------- zero both Z arrays ----------------
__global__ void zero_kern() {
    int i = blockIdx.x * 256 + threadIdx.x;
    if (i < BB * LL) { g_Zr[i] = 0.f; g_Zc[i] = 0.f; }
}

// ---------------- unified GEMM kernel (3-stage cp.async, 1 sync/chunk) ----------------
// MODE 0: E = exp(scale * x1 X2h^T) -> fp16; row/col sums fused via atomics.
//         2 phases: X1h*X2h + X1l*X2h   (dropped x1*X2l term ~1.5e-4)
// MODE 1: out  = diag(1/Zr) * E * x2      (B = X2T splits, 2 phases)
// MODE 2: out += diag(1/Zc) * E^T * x1    (A = E via ldsm.trans, 2 phases)
template <int MODE>
__global__ void __launch_bounds__(256)
gemm_kern(float* __restrict__ Out)
{
    constexpr int KP  = (MODE == 0) ? DD : LL;
    constexpr int NKC = KP / 64;
    constexpr int NCH = 2 * NKC;
    constexpr int LDA = (MODE == 0) ? DD : LL;
    constexpr int LDB = (MODE == 0) ? DD : LL;
    constexpr int PA = 72, PA2 = 136, PB = 72;
    constexpr int ASZ = (MODE == 2) ? 64 * PA2 : 128 * PA;
    constexpr int BSZ = 128 * PB;

    extern __shared__ hf sm[];
    hf* Asm = sm;                  // 3 stages of ASZ
    hf* Bsm = sm + 3 * ASZ;        // 3 stages of BSZ
    __shared__ float sZr[128], sZc[128];

    const int t = threadIdx.x, lane = t & 31, warp = t >> 5;
    const int wm = warp >> 2, wn = warp & 3;
    const int bN = blockIdx.x, bM = blockIdx.y, b = blockIdx.z;
    const int m0 = bM * 128, n0 = bN * 128;

    if (MODE == 0 && t < 128) { sZr[t] = 0.f; sZc[t] = 0.f; }

    const size_t ab = (MODE == 0) ? (size_t)b * LL * DD : (size_t)b * LL * LL;
    const size_t bb = (MODE == 0) ? (size_t)b * LL * DD : (size_t)b * DD * LL;
    const hf* Ap[2]; const hf* Bp[2];
    if (MODE == 0) {
        Ap[0] = g_X1h + ab; Ap[1] = g_X1l + ab;
        Bp[0] = g_X2h + bb; Bp[1] = g_X2h + bb;
    } else if (MODE == 1) {
        Ap[0] = g_E + ab;   Ap[1] = g_E + ab;
        Bp[0] = g_X2Th + bb; Bp[1] = g_X2Tl + bb;
    } else {
        Ap[0] = g_E + ab;   Ap[1] = g_E + ab;
        Bp[0] = g_X1Th + bb; Bp[1] = g_X1Tl + bb;
    }

    float acc[4][4][4];
    #pragma unroll
    for (int j = 0; j < 4; ++j)
        #pragma unroll
        for (int n = 0; n < 4; ++n)
            #pragma unroll
            for (int i = 0; i < 4; ++i) acc[j][n][i] = 0.f;

    auto loadA = [&](int c, int buf) {
        const hf* src = Ap[c / NKC];
        int k0 = (c % NKC) * 64;
        if (MODE == 2) {
            #pragma unroll
            for (int i = 0; i < 4; ++i) {
                int idx = t + i * 256, r = idx >> 4, s8 = idx & 15;
                cp_async16(Asm + buf * ASZ + r * PA2 + s8 * 8,
                           src + (size_t)(k0 + r) * LDA + m0 + s8 * 8);
            }
        } else {
            #pragma unroll
            for (int i = 0; i < 4; ++i) {
                int idx = t + i * 256, r = idx >> 3, s8 = idx & 7;
                cp_async16(Asm + buf * ASZ + r * PA + s8 * 8,
                           src + (size_t)(m0 + r) * LDA + k0 + s8 * 8);
            }
        }
    };
    auto loadB = [&](int c, int buf) {
        const hf* src = Bp[c / NKC];
        int k0 = (c % NKC) * 64;
        #pragma unroll
        for (int i = 0; i < 4; ++i) {
            int idx = t + i * 256, r = idx >> 3, s8 = idx & 7;
            cp_async16(Bsm + buf * BSZ + r * PB + s8 * 8,
                       src + (size_t)(n0 + r) * LDB + k0 + s8 * 8);
        }
    };
    auto comp = [&](int buf) {
        const hf* At = Asm + buf * ASZ;
        const hf* Bt = Bsm + buf * BSZ;
        #pragma unroll
        for (int k16 = 0; k16 < 4; ++k16) {
            unsigned bfr[4][2];
            #pragma unroll
            for (int nb = 0; nb < 2; ++nb) {
                unsigned r[4];
                ldsm4(r, scvt(Bt + (wn * 32 + nb * 16 + (lane & 15)) * PB
                                 + k16 * 16 + (lane >> 4) * 8));
                bfr[nb * 2 + 0][0] = r[0]; bfr[nb * 2 + 0][1] = r[2];
                bfr[nb * 2 + 1][0] = r[1]; bfr[nb * 2 + 1][1] = r[3];
            }
            unsigned afr[4][4];
            #pragma unroll
            for (int j = 0; j < 4; ++j) {
                if (MODE == 2) {
                    ldsm4t(afr[j], scvt(At + (k16 * 16 + (lane & 7) + ((lane >> 4) & 1) * 8) * PA2
                                           + wm * 64 + j * 16 + ((lane >> 3) & 1) * 8));
                } else {
                    ldsm4(afr[j], scvt(At + (wm * 64 + j * 16 + (lane & 15)) * PA
                                          + k16 * 16 + (lane >> 4) * 8));
                }
            }
            #pragma unroll
            for (int j = 0; j < 4; ++j)
                #pragma unroll
                for (int n = 0; n < 4; ++n)
                    mma16816(acc[j][n], afr[j], bfr[n]);
        }
    };

    // 3-stage pipeline: stages c, c+1 in flight; refill c+2 each iteration.
    loadA(0, 0); loadB(0, 0); cp_commit();
    loadA(1, 1); loadB(1, 1); cp_commit();
    for (int c = 0; c < NCH; ++c) {
        if (c == NCH - 1) cp_wait0(); else cp_wait1();   // stage c landed
        __syncthreads();                                  // also: everyone done with comp(c-1)
        if (c + 2 < NCH) {
            int nb = (c + 2) % 3;                         // == (c-1)%3, safe after sync
            loadA(c + 2, nb); loadB(c + 2, nb); cp_commit();
        }
        comp(c % 3);
    }

    // ---------------- epilogue ----------------
    const float scale = 0.044194173824159216f;
    if (MODE == 0) {
        float cp[4][2];
        #pragma unroll
        for (int jn = 0; jn < 4; ++jn) { cp[jn][0] = 0.f; cp[jn][1] = 0.f; }
        #pragma unroll
        for (int j = 0; j < 4; ++j) {
            int rloc = wm * 64 + j * 16 + (lane >> 2);
            int rglob = m0 + rloc;
            float rp0 = 0.f, rp1 = 0.f;
            #pragma unroll
            for (int jn = 0; jn < 4; ++jn) {
                int cc = n0 + wn * 32 + jn * 8 + 2 * (lane & 3);
                float* a = acc[j][jn];
                hf h00 = __float2half_rn(__expf(scale * a[0]));
                hf h01 = __float2half_rn(__expf(scale * a[1]));
                hf h10 = __float2half_rn(__expf(scale * a[2]));
                hf h11 = __float2half_rn(__expf(scale * a[3]));
                size_t o0 = ((size_t)b * LL + rglob) * LL + cc;
                size_t o1 = ((size_t)b * LL + rglob + 8) * LL + cc;
                *(__half2*)&g_E[o0] = __halves2half2(h00, h01);
                *(__half2*)&g_E[o1] = __halves2half2(h10, h11);
                float v00 = __half2float(h00), v01 = __half2float(h01);
                float v10 = __half2float(h10), v11 = __half2float(h11);
                rp0 += v00 + v01;  rp1 += v10 + v11;
                cp[jn][0] += v00 + v10;  cp[jn][1] += v01 + v11;
            }
            rp0 += __shfl_xor_sync(0xffffffffu, rp0, 1);
            rp0 += __shfl_xor_sync(0xffffffffu, rp0, 2);
            rp1 += __shfl_xor_sync(0xffffffffu, rp1, 1);
            rp1 += __shfl_xor_sync(0xffffffffu, rp1, 2);
            if ((lane & 3) == 0) {
                atomicAdd(&sZr[rloc], rp0);
                atomicAdd(&sZr[rloc + 8], rp1);
            }
        }
        #pragma unroll
        for (int jn = 0; jn < 4; ++jn)
            #pragma unroll
            for (int i = 0; i < 2; ++i) {
                float v = cp[jn][i];
                v += __shfl_xor_sync(0xffffffffu, v, 4);
                v += __shfl_xor_sync(0xffffffffu, v, 8);
                v += __shfl_xor_sync(0xffffffffu, v, 16);
                if (lane < 4)
                    atomicAdd(&sZc[wn * 32 + jn * 8 + 2 * lane + i], v);
            }
        __syncthreads();
        if (t < 128) {
            atomicAdd(&g_Zr[b * LL + m0 + t], sZr[t]);
            atomicAdd(&g_Zc[b * LL + n0 + t], sZc[t]);
        }
    } else {
        const float* Zs = (MODE == 1) ? g_Zr : g_Zc;
        #pragma unroll
        for (int j = 0; j < 4; ++j) {
            int r0 = m0 + wm * 64 + j * 16 + (lane >> 2);
            float f0 = __frcp_rn(Zs[b * LL + r0]);
            float f1 = __frcp_rn(Zs[b * LL + r0 + 8]);
            #pragma unroll
            for (int jn = 0; jn < 4; ++jn) {
                int cc = n0 + wn * 32 + jn * 8 + 2 * (lane & 3);
                float* a = acc[j][jn];
                float2* p0 = (float2*)(Out + ((size_t)b * LL + r0) * DD + cc);
                float2* p1 = (float2*)(Out + ((size_t)b * LL + r0 + 8) * DD + cc);
                if (MODE == 1) {
                    *p0 = make_float2(a[0] * f0, a[1] * f0);
                    *p1 = make_float2(a[2] * f1, a[3] * f1);
                } else {
                    float2 v0 = *p0; v0.x += a[0] * f0; v0.y += a[1] * f0; *p0 = v0;
                    float2 v1 = *p1; v1.x += a[2] * f1; v1.y += a[3] * f1; *p1 = v1;
                }
            }
        }
    }
}

// ---------------- launch ----------------
extern "C" void kernel_launch(void* const* d_in, const int* in_sizes, int n_in,
                              void* d_out, int out_size)
{
    (void)in_sizes; (void)n_in; (void)out_size;
    const float* x1 = (const float*)d_in[0];
    const float* x2 = (const float*)d_in[1];
    float* out = (float*)d_out;

    const int SM01 = 3 * (128 * 72 + 128 * 72) * 2;   // 110592 B -> 2 CTAs/SM
    const int SM2  = 3 * (64 * 136 + 128 * 72) * 2;   // 107520 B
    cudaFuncSetAttribute(gemm_kern<0>, cudaFuncAttributeMaxDynamicSharedMemorySize, SM01);
    cudaFuncSetAttribute(gemm_kern<1>, cudaFuncAttributeMaxDynamicSharedMemorySize, SM01);
    cudaFuncSetAttribute(gemm_kern<2>, cudaFuncAttributeMaxDynamicSharedMemorySize, SM2);

    zero_kern<<<64, 256>>>();
    prep_kern<<<dim3(LL / 32, DD / 32, 2 * BB), dim3(32, 8)>>>(x1, x2);
    gemm_kern<0><<<dim3(LL / 128, LL / 128, BB), 256, SM01>>>(nullptr);  // E + fused Zr/Zc
    gemm_kern<1><<<dim3(DD / 128, LL / 128, BB), 256, SM01>>>(out);      // out  = P  x2
    gemm_kern<2><<<dim3(DD / 128, LL / 128, BB), 256, SM2 >>>(out);      // out += Pc x1
}